// round 9
// baseline (speedup 1.0000x reference)
#include <cuda_runtime.h>
#include <cuda_bf16.h>
#include <cstdint>
#include <cstddef>

// ---------------------------------------------------------------------------
// Problem constants
// ---------------------------------------------------------------------------
#define GH 6
#define GM 512          // batch
#define GN 1000         // classes
#define GNP 1024        // padded classes
#define GK 2048         // feature dim
#define TAUC 0.5f

// GEMM tiling (mma.sync, 4-stage pipeline)
#define BM 64
#define BN 128
#define BK 32                     // bf16 elems per stage (64 B rows)
#define NKB (GK / BK)             // 64 stages
#define NSTAGE 4
#define A_TILE_B (BM * 64)        // 4096 B per A split tile
#define B_TILE_B (BN * 64)        // 8192 B per B split tile
#define STAGE_B (2 * A_TILE_B + 2 * B_TILE_B)   // 24576 B
#define SMEM_DYN (NSTAGE * STAGE_B + 1024)

// ---------------------------------------------------------------------------
// Device-global scratch (no allocation allowed)
// ---------------------------------------------------------------------------
__device__ __align__(16) __nv_bfloat16 g_fa0[GH * GM * GK];
__device__ __align__(16) __nv_bfloat16 g_fa1[GH * GM * GK];
__device__ __align__(16) __nv_bfloat16 g_wt0[GH * GNP * GK];
__device__ __align__(16) __nv_bfloat16 g_wt1[GH * GNP * GK];
__device__ float g_logits[GH * GM * GN];
__device__ float g_lse   [GH * GM];
__device__ float g_conf  [GH * GM];
__device__ int   g_amax  [GH * GM];
__device__ int   g_exit  [GM];

// ---------------------------------------------------------------------------
// Helpers (baseline PTX only — safe on plain sm_103 target)
// ---------------------------------------------------------------------------
__device__ __forceinline__ uint32_t smem_to_u32(const void* p) {
    uint32_t a;
    asm("{ .reg .u64 t; cvta.to.shared.u64 t, %1; cvt.u32.u64 %0, t; }"
        : "=r"(a) : "l"(p));
    return a;
}

__device__ __forceinline__ void cp16(uint32_t s, const void* g) {
    asm volatile("cp.async.cg.shared.global [%0], [%1], 16;\n" :: "r"(s), "l"(g));
}
#define CP_COMMIT() asm volatile("cp.async.commit_group;\n" ::: "memory")
#define CP_WAIT2()  asm volatile("cp.async.wait_group 2;\n" ::: "memory")

__device__ __forceinline__ void ldmx4(uint32_t* r, uint32_t addr) {
    asm volatile("ldmatrix.sync.aligned.m8n8.x4.shared.b16 {%0,%1,%2,%3}, [%4];"
                 : "=r"(r[0]), "=r"(r[1]), "=r"(r[2]), "=r"(r[3]) : "r"(addr));
}

__device__ __forceinline__ void mma16816(float* c, const uint32_t* a, const uint32_t* b) {
    asm volatile(
        "mma.sync.aligned.m16n8k16.row.col.f32.bf16.bf16.f32 "
        "{%0,%1,%2,%3}, {%4,%5,%6,%7}, {%8,%9}, {%0,%1,%2,%3};"
        : "+f"(c[0]), "+f"(c[1]), "+f"(c[2]), "+f"(c[3])
        : "r"(a[0]), "r"(a[1]), "r"(a[2]), "r"(a[3]), "r"(b[0]), "r"(b[1]));
}

// swizzled byte offset within a tile: 64B rows, 16B chunks, XOR with (row>>1)&3
__device__ __forceinline__ uint32_t swz(int row, int ch) {
    return (uint32_t)(row * 64 + ((ch ^ ((row >> 1) & 3)) << 4));
}

// ---------------------------------------------------------------------------
// Kernel A: convert feats fp32 -> 2 bf16 splits
// ---------------------------------------------------------------------------
__device__ __forceinline__ void split2(float v, __nv_bfloat16& s0, __nv_bfloat16& s1) {
    s0 = __float2bfloat16_rn(v);
    s1 = __float2bfloat16_rn(v - __bfloat162float(s0));
}

__global__ __launch_bounds__(256) void convert_feats_kernel(const float* __restrict__ feats)
{
    const int gid = blockIdx.x * 256 + threadIdx.x;   // one per 4 elems
    float4 v = reinterpret_cast<const float4*>(feats)[gid];
    __nv_bfloat16 a0[4], a1[4];
    split2(v.x, a0[0], a1[0]);
    split2(v.y, a0[1], a1[1]);
    split2(v.z, a0[2], a1[2]);
    split2(v.w, a0[3], a1[3]);
    reinterpret_cast<uint2*>(g_fa0)[gid] = *reinterpret_cast<uint2*>(a0);
    reinterpret_cast<uint2*>(g_fa1)[gid] = *reinterpret_cast<uint2*>(a1);
}

// ---------------------------------------------------------------------------
// Kernel B: transpose + convert W [h,2048,1000] fp32 -> Wt [h,1024,2048] bf16 x2
// 64k x 32c tiles, packed uint32 (2 bf16) coalesced stores.
// ---------------------------------------------------------------------------
__global__ __launch_bounds__(256) void convert_w_kernel(const float* __restrict__ W)
{
    const int h  = blockIdx.z;
    const int k0 = blockIdx.y * 64;
    const int c0 = blockIdx.x * 32;
    __shared__ float t[64][33];
    const int tid  = threadIdx.x;
    const int lane = tid & 31;
    const int wid  = tid >> 5;    // 0..7

    // Load 64 k-rows x 32 c-cols, coalesced over c
    #pragma unroll
    for (int it = 0; it < 8; it++) {
        int r = it * 8 + wid;              // local k
        int c = c0 + lane;
        t[r][lane] = (c < GN) ? W[((size_t)h * GK + (k0 + r)) * GN + c] : 0.0f;
    }
    __syncthreads();

    // Write: warp w handles column cl = p*8 + w; lane handles k-pair 2*lane
    #pragma unroll
    for (int p = 0; p < 4; p++) {
        const int cl = p * 8 + wid;        // local c 0..31
        const int cg = c0 + cl;
        float v0 = t[2 * lane][cl];
        float v1 = t[2 * lane + 1][cl];
        __nv_bfloat16 a0, a1, b0, b1;
        split2(v0, a0, a1);
        split2(v1, b0, b1);
        __nv_bfloat162 p0, p1;
        p0.x = a0; p0.y = b0;              // split-0 pair (k, k+1)
        p1.x = a1; p1.y = b1;              // split-1 pair
        size_t widx = (((size_t)h * GNP + cg) * GK + k0 + 2 * lane) >> 1;
        reinterpret_cast<uint32_t*>(g_wt0)[widx] = *reinterpret_cast<uint32_t*>(&p0);
        reinterpret_cast<uint32_t*>(g_wt1)[widx] = *reinterpret_cast<uint32_t*>(&p1);
    }
}

// ---------------------------------------------------------------------------
// Kernel C: mma.sync bf16 GEMM (3-product fp32 emulation), 4-stage pipeline
// ---------------------------------------------------------------------------
__device__ __forceinline__ void load_stage(
    uint32_t sb, int kb, int tid,
    const __nv_bfloat16* const* srcs)
{
    // A tiles (0..1): 256 chunks each (64 rows x 4 ch)
    {
        const int row = tid >> 2;
        const int ch  = tid & 3;
        #pragma unroll
        for (int i = 0; i < 2; i++) {
            const __nv_bfloat16* g = srcs[i] + (size_t)row * GK + kb * BK + ch * 8;
            cp16(sb + i * A_TILE_B + swz(row, ch), g);
        }
    }
    // B tiles (2..3): 512 chunks each = 2 iters of 256
    #pragma unroll
    for (int i = 0; i < 2; i++)
        #pragma unroll
        for (int it = 0; it < 2; it++) {
            const int q   = it * 256 + tid;
            const int row = q >> 2;
            const int ch  = q & 3;
            const __nv_bfloat16* g = srcs[2 + i] + (size_t)row * GK + kb * BK + ch * 8;
            cp16(sb + 2 * A_TILE_B + i * B_TILE_B + swz(row, ch), g);
        }
}

__global__ __launch_bounds__(256, 2) void sdn_mma_gemm(const float* __restrict__ bias)
{
    extern __shared__ char smem[];
    const uint32_t sm0 = (smem_to_u32(smem) + 1023u) & ~1023u;

    const int tid  = threadIdx.x;
    const int wid  = tid >> 5;
    const int lane = tid & 31;
    const int wm   = (wid & 1) * 32;        // 2 warps along m
    const int wn   = (wid >> 1) * 32;       // 4 warps along n

    const int h  = blockIdx.z;
    const int m0 = blockIdx.y * BM;
    const int n0 = blockIdx.x * BN;

    const __nv_bfloat16* srcs[4] = {
        g_fa0 + ((size_t)h * GM  + m0) * GK,
        g_fa1 + ((size_t)h * GM  + m0) * GK,
        g_wt0 + ((size_t)h * GNP + n0) * GK,
        g_wt1 + ((size_t)h * GNP + n0) * GK
    };

    float acc[2][4][4];
    #pragma unroll
    for (int f = 0; f < 2; f++)
        #pragma unroll
        for (int n = 0; n < 4; n++)
            #pragma unroll
            for (int e = 0; e < 4; e++) acc[f][n][e] = 0.0f;

    // Prologue: fill stages 0..2
    #pragma unroll
    for (int s = 0; s < NSTAGE - 1; s++) {
        load_stage(sm0 + s * STAGE_B, s, tid, srcs);
        CP_COMMIT();
    }

    #pragma unroll 1
    for (int kb = 0; kb < NKB; kb++) {
        CP_WAIT2();              // stage kb now resident
        __syncthreads();         // also proves all warps finished stage kb-1 reads

        // Prefetch stage kb+3 into the slot freed by stage kb-1
        if (kb + NSTAGE - 1 < NKB)
            load_stage(sm0 + ((kb + NSTAGE - 1) & (NSTAGE - 1)) * STAGE_B,
                       kb + NSTAGE - 1, tid, srcs);
        CP_COMMIT();             // unconditional: keeps group accounting uniform

        const uint32_t sb = sm0 + (kb & (NSTAGE - 1)) * STAGE_B;
        #pragma unroll
        for (int ks = 0; ks < 2; ks++) {
            uint32_t ra[2][2][4];
            #pragma unroll
            for (int s = 0; s < 2; s++)
                #pragma unroll
                for (int f = 0; f < 2; f++) {
                    int row = wm + f * 16 + (lane & 15);
                    int ch  = 2 * ks + (lane >> 4);
                    ldmx4(ra[s][f], sb + s * A_TILE_B + swz(row, ch));
                }
            uint32_t rb[2][2][4];
            #pragma unroll
            for (int s = 0; s < 2; s++)
                #pragma unroll
                for (int g = 0; g < 2; g++) {
                    int row = wn + g * 16 + (lane & 7) + ((lane >> 4) << 3);
                    int ch  = 2 * ks + ((lane >> 3) & 1);
                    ldmx4(rb[s][g], sb + 2 * A_TILE_B + s * B_TILE_B + swz(row, ch));
                }
            const int PA[3] = {0, 0, 1};
            const int PB[3] = {0, 1, 0};
            #pragma unroll
            for (int p = 0; p < 3; p++)
                #pragma unroll
                for (int f = 0; f < 2; f++)
                    #pragma unroll
                    for (int g = 0; g < 2; g++)
                        #pragma unroll
                        for (int h2 = 0; h2 < 2; h2++)
                            mma16816(acc[f][g * 2 + h2],
                                     ra[PA[p]][f], &rb[PB[p]][g][h2 * 2]);
        }
    }

    // Epilogue: add bias, store fp32 logits
    const int g8  = lane >> 2;
    const int tig = lane & 3;
    #pragma unroll
    for (int f = 0; f < 2; f++) {
        #pragma unroll
        for (int nf = 0; nf < 4; nf++) {
            const int mrow = m0 + wm + f * 16 + g8;
            const int ncol = n0 + wn + nf * 8 + tig * 2;
            float* o0 = g_logits + ((size_t)h * GM + mrow) * GN;
            float* o1 = g_logits + ((size_t)h * GM + mrow + 8) * GN;
            if (ncol < GN) {
                float bz = bias[h * GN + ncol];
                o0[ncol] = acc[f][nf][0] + bz;
                o1[ncol] = acc[f][nf][2] + bz;
            }
            if (ncol + 1 < GN) {
                float bz = bias[h * GN + ncol + 1];
                o0[ncol + 1] = acc[f][nf][1] + bz;
                o1[ncol + 1] = acc[f][nf][3] + bz;
            }
        }
    }
}

// ---------------------------------------------------------------------------
// Kernel D: per-row stats (max, argmax, logsumexp, conf) — register-cached
// ---------------------------------------------------------------------------
__global__ __launch_bounds__(128) void sdn_rowstats_kernel()
{
    const int row = blockIdx.x;
    const float* p = g_logits + (size_t)row * GN;
    const int tid = threadIdx.x;

    float v[8];
    #pragma unroll
    for (int i = 0; i < 8; i++) {
        int c = tid + i * 128;
        v[i] = (c < GN) ? p[c] : -1e30f;
    }

    float vmax = -1e30f;
    int   vidx = 0;
    #pragma unroll
    for (int i = 0; i < 8; i++)
        if (v[i] > vmax) { vmax = v[i]; vidx = tid + i * 128; }

    __shared__ float smax[128];
    __shared__ int   sidx[128];
    smax[tid] = vmax; sidx[tid] = vidx;
    __syncthreads();
    for (int s = 64; s > 0; s >>= 1) {
        if (tid < s) {
            float ov = smax[tid + s]; int oi = sidx[tid + s];
            if (ov > smax[tid] || (ov == smax[tid] && oi < sidx[tid])) {
                smax[tid] = ov; sidx[tid] = oi;
            }
        }
        __syncthreads();
    }
    const float rmax = smax[0];

    float sum = 0.0f;
    #pragma unroll
    for (int i = 0; i < 8; i++)
        sum += expf(v[i] - rmax);

    __shared__ float ssum[128];
    ssum[tid] = sum;
    __syncthreads();
    for (int s = 64; s > 0; s >>= 1) {
        if (tid < s) ssum[tid] += ssum[tid + s];
        __syncthreads();
    }
    if (tid == 0) {
        float lse = rmax + logf(ssum[0]);
        g_lse[row]  = lse;
        g_conf[row] = expf(rmax - lse);
        g_amax[row] = sidx[0];
    }
}

// ---------------------------------------------------------------------------
// Kernel E: routing + loss + acc
// ---------------------------------------------------------------------------
__global__ __launch_bounds__(512) void sdn_route_kernel(
    const int* __restrict__ y_true, float* __restrict__ out)
{
    const int b = threadIdx.x;

    int   firstExit = -1;
    float bestc = -1e30f;
    int   besth = 0;
    #pragma unroll
    for (int h = 0; h < GH; h++) {
        float c = g_conf[h * GM + b];
        if (firstExit < 0 && c >= TAUC) firstExit = h;
        if (c > bestc) { bestc = c; besth = h; }
    }
    const int ex = (firstExit >= 0) ? firstExit : besth;
    g_exit[b] = ex;

    const int y = y_true[b];
    const size_t rowbase = ((size_t)ex * GM + b);
    const float logit_y = g_logits[rowbase * GN + y];
    const float loss_b  = -(logit_y - g_lse[rowbase]);
    const float acc_b   = (g_amax[rowbase] == y) ? 1.0f : 0.0f;

    out[GM * GN + b] = (float)ex;

    __shared__ float sl[512];
    __shared__ float sa[512];
    sl[b] = loss_b; sa[b] = acc_b;
    __syncthreads();
    for (int s = 256; s > 0; s >>= 1) {
        if (b < s) { sl[b] += sl[b + s]; sa[b] += sa[b + s]; }
        __syncthreads();
    }
    if (b == 0) {
        out[GM * GN + GM + 0] = sl[0] / (float)GM;
        out[GM * GN + GM + 1] = sa[0] / (float)GM;
    }
}

// ---------------------------------------------------------------------------
// Kernel F: gather routed outputs
// ---------------------------------------------------------------------------
__global__ __launch_bounds__(256) void sdn_gather_kernel(float* __restrict__ out)
{
    const int b  = blockIdx.x;
    const int ex = g_exit[b];
    const float4* src = reinterpret_cast<const float4*>(
        g_logits + ((size_t)ex * GM + b) * GN);
    float4* dst = reinterpret_cast<float4*>(out + (size_t)b * GN);
    for (int i = threadIdx.x; i < GN / 4; i += blockDim.x)
        dst[i] = src[i];
}

// ---------------------------------------------------------------------------
extern "C" void kernel_launch(void* const* d_in, const int* in_sizes, int n_in,
                              void* d_out, int out_size)
{
    const float* feats = (const float*)d_in[0];  // [6,512,2048]
    const float* W     = (const float*)d_in[1];  // [6,2048,1000]
    const float* bias  = (const float*)d_in[2];  // [6,1000]
    const int*   y     = (const int*)  d_in[3];  // [512]
    float* out = (float*)d_out;

    cudaFuncSetAttribute(sdn_mma_gemm, cudaFuncAttributeMaxDynamicSharedMemorySize, SMEM_DYN);

    convert_feats_kernel<<<(GH * GM * GK / 4) / 256, 256>>>(feats);
    convert_w_kernel<<<dim3(GNP / 32, GK / 64, GH), 256>>>(W);
    sdn_mma_gemm<<<dim3(GNP / BN, GM / BM, GH), 256, SMEM_DYN>>>(bias);
    sdn_rowstats_kernel<<<GH * GM, 128>>>();
    sdn_route_kernel<<<1, 512>>>(y, out);
    sdn_gather_kernel<<<GM, 256>>>(out);
}

// round 10
// speedup vs baseline: 1.1212x; 1.1212x over previous
#include <cuda_runtime.h>
#include <cuda_bf16.h>
#include <cstdint>
#include <cstddef>

// ---------------------------------------------------------------------------
// Problem constants
// ---------------------------------------------------------------------------
#define GH 6
#define GM 512          // batch
#define GN 1000         // classes
#define GNP 1024        // padded classes
#define GK 2048         // feature dim
#define TAUC 0.5f
#define NTILES_N 8      // GNP / BN

// GEMM tiling (R7 proven config: BK=64, 2-stage)
#define BM 64
#define BN 128
#define BK 64                     // bf16 elems per stage (128 B rows)
#define NKB (GK / BK)             // 32 stages
#define A_TILE_B (BM * 128)       // 8192 B per A split tile
#define B_TILE_B (BN * 128)       // 16384 B per B split tile
#define STAGE_B (2 * A_TILE_B + 2 * B_TILE_B)   // 49152 B
#define SMEM_DYN (2 * STAGE_B + 1024)

#define NFBLK 6144                // convert: feats blocks
#define NWBLK 6144                // convert: W blocks (32 c-tiles x 32 k-tiles x 6 h)

// ---------------------------------------------------------------------------
// Device-global scratch (no allocation allowed)
// ---------------------------------------------------------------------------
__device__ __align__(16) __nv_bfloat16 g_fa0[GH * GM * GK];
__device__ __align__(16) __nv_bfloat16 g_fa1[GH * GM * GK];
__device__ __align__(16) __nv_bfloat16 g_wt0[GH * GNP * GK];
__device__ __align__(16) __nv_bfloat16 g_wt1[GH * GNP * GK];
__device__ float g_logits[GH * GM * GN];
__device__ float g_pmax[GH * GM * NTILES_N];
__device__ float g_psum[GH * GM * NTILES_N];
__device__ int   g_pidx[GH * GM * NTILES_N];
__device__ float g_lse   [GH * GM];
__device__ float g_conf  [GH * GM];
__device__ int   g_amax  [GH * GM];
__device__ int   g_exit  [GM];

// ---------------------------------------------------------------------------
// Helpers (baseline PTX only — safe on plain sm_103 target)
// ---------------------------------------------------------------------------
__device__ __forceinline__ uint32_t smem_to_u32(const void* p) {
    uint32_t a;
    asm("{ .reg .u64 t; cvta.to.shared.u64 t, %1; cvt.u32.u64 %0, t; }"
        : "=r"(a) : "l"(p));
    return a;
}

__device__ __forceinline__ void cp16(uint32_t s, const void* g) {
    asm volatile("cp.async.cg.shared.global [%0], [%1], 16;\n" :: "r"(s), "l"(g));
}
#define CP_COMMIT() asm volatile("cp.async.commit_group;\n" ::: "memory")
#define CP_WAIT1()  asm volatile("cp.async.wait_group 1;\n" ::: "memory")
#define CP_WAIT0()  asm volatile("cp.async.wait_group 0;\n" ::: "memory")

__device__ __forceinline__ void ldmx4(uint32_t* r, uint32_t addr) {
    asm volatile("ldmatrix.sync.aligned.m8n8.x4.shared.b16 {%0,%1,%2,%3}, [%4];"
                 : "=r"(r[0]), "=r"(r[1]), "=r"(r[2]), "=r"(r[3]) : "r"(addr));
}

__device__ __forceinline__ void mma16816(float* c, const uint32_t* a, const uint32_t* b) {
    asm volatile(
        "mma.sync.aligned.m16n8k16.row.col.f32.bf16.bf16.f32 "
        "{%0,%1,%2,%3}, {%4,%5,%6,%7}, {%8,%9}, {%0,%1,%2,%3};"
        : "+f"(c[0]), "+f"(c[1]), "+f"(c[2]), "+f"(c[3])
        : "r"(a[0]), "r"(a[1]), "r"(a[2]), "r"(a[3]), "r"(b[0]), "r"(b[1]));
}

// swizzled byte offset within a tile: 128B rows, 16B chunks, xor-8
__device__ __forceinline__ uint32_t swz(int row, int ch) {
    return (uint32_t)(row * 128 + ((ch ^ (row & 7)) << 4));
}

__device__ __forceinline__ void split2(float v, __nv_bfloat16& s0, __nv_bfloat16& s1) {
    s0 = __float2bfloat16_rn(v);
    s1 = __float2bfloat16_rn(v - __bfloat162float(s0));
}

// ---------------------------------------------------------------------------
// Kernel A: merged converts.
//   blocks [0, NFBLK)          : feats fp32 -> 2 bf16 splits
//   blocks [NFBLK, NFBLK+NWBLK): W transpose+split, 64k x 32c tiles
// ---------------------------------------------------------------------------
__global__ __launch_bounds__(256) void convert_all_kernel(
    const float* __restrict__ feats, const float* __restrict__ W)
{
    const int bid = blockIdx.x;
    if (bid < NFBLK) {
        const int gid = bid * 256 + threadIdx.x;   // one per 4 elems
        float4 v = reinterpret_cast<const float4*>(feats)[gid];
        __nv_bfloat16 a0[4], a1[4];
        split2(v.x, a0[0], a1[0]);
        split2(v.y, a0[1], a1[1]);
        split2(v.z, a0[2], a1[2]);
        split2(v.w, a0[3], a1[3]);
        reinterpret_cast<uint2*>(g_fa0)[gid] = *reinterpret_cast<uint2*>(a0);
        reinterpret_cast<uint2*>(g_fa1)[gid] = *reinterpret_cast<uint2*>(a1);
    } else {
        const int wb = bid - NFBLK;                // 0..6143
        const int h  = wb >> 10;                   // /1024
        const int k0 = ((wb >> 5) & 31) * 64;
        const int c0 = (wb & 31) * 32;
        __shared__ float t[64][33];
        const int tid  = threadIdx.x;
        const int lane = tid & 31;
        const int wid  = tid >> 5;                 // 0..7

        #pragma unroll
        for (int it = 0; it < 8; it++) {
            int r = it * 8 + wid;                  // local k
            int c = c0 + lane;
            t[r][lane] = (c < GN) ? W[((size_t)h * GK + (k0 + r)) * GN + c] : 0.0f;
        }
        __syncthreads();

        #pragma unroll
        for (int p = 0; p < 4; p++) {
            const int cl = p * 8 + wid;            // local c 0..31
            const int cg = c0 + cl;
            float v0 = t[2 * lane][cl];
            float v1 = t[2 * lane + 1][cl];
            __nv_bfloat16 a0, a1, b0, b1;
            split2(v0, a0, a1);
            split2(v1, b0, b1);
            __nv_bfloat162 p0, p1;
            p0.x = a0; p0.y = b0;
            p1.x = a1; p1.y = b1;
            size_t widx = (((size_t)h * GNP + cg) * GK + k0 + 2 * lane) >> 1;
            reinterpret_cast<uint32_t*>(g_wt0)[widx] = *reinterpret_cast<uint32_t*>(&p0);
            reinterpret_cast<uint32_t*>(g_wt1)[widx] = *reinterpret_cast<uint32_t*>(&p1);
        }
    }
}

// ---------------------------------------------------------------------------
// Kernel B: mma.sync bf16 GEMM (3-product fp32 emulation, R7 core) +
//           fused bias + per-tile softmax partial stats in the epilogue.
// ---------------------------------------------------------------------------
__device__ __forceinline__ void load_stage(
    uint32_t sb, int kb, int tid,
    const __nv_bfloat16* const* srcs)
{
    #pragma unroll
    for (int i = 0; i < 2; i++)
        #pragma unroll
        for (int it = 0; it < 2; it++) {
            const int q   = it * 256 + tid;
            const int row = q >> 3;
            const int ch  = q & 7;
            const __nv_bfloat16* g = srcs[i] + (size_t)row * GK + kb * BK + ch * 8;
            cp16(sb + i * A_TILE_B + swz(row, ch), g);
        }
    #pragma unroll
    for (int i = 0; i < 2; i++)
        #pragma unroll
        for (int it = 0; it < 4; it++) {
            const int q   = it * 256 + tid;
            const int row = q >> 3;
            const int ch  = q & 7;
            const __nv_bfloat16* g = srcs[2 + i] + (size_t)row * GK + kb * BK + ch * 8;
            cp16(sb + 2 * A_TILE_B + i * B_TILE_B + swz(row, ch), g);
        }
}

__global__ __launch_bounds__(256, 2) void sdn_mma_gemm(const float* __restrict__ bias)
{
    extern __shared__ char smem[];
    const uint32_t sm0 = (smem_to_u32(smem) + 1023u) & ~1023u;

    __shared__ float s_pm[2][32][4];
    __shared__ float s_ps[2][32][4];
    __shared__ int   s_pi[2][32][4];

    const int tid  = threadIdx.x;
    const int wid  = tid >> 5;
    const int lane = tid & 31;
    const int wm   = (wid & 1) * 32;        // 2 warps along m
    const int wn   = (wid >> 1) * 32;       // 4 warps along n
    const int wmg  = wid & 1;
    const int wnid = wid >> 1;

    const int h  = blockIdx.z;
    const int m0 = blockIdx.y * BM;
    const int n0 = blockIdx.x * BN;

    const __nv_bfloat16* srcs[4] = {
        g_fa0 + ((size_t)h * GM  + m0) * GK,
        g_fa1 + ((size_t)h * GM  + m0) * GK,
        g_wt0 + ((size_t)h * GNP + n0) * GK,
        g_wt1 + ((size_t)h * GNP + n0) * GK
    };

    float acc[2][4][4];
    #pragma unroll
    for (int f = 0; f < 2; f++)
        #pragma unroll
        for (int n = 0; n < 4; n++)
            #pragma unroll
            for (int e = 0; e < 4; e++) acc[f][n][e] = 0.0f;

    // Prologue
    load_stage(sm0, 0, tid, srcs);
    CP_COMMIT();

    #pragma unroll 1
    for (int kb = 0; kb < NKB; kb++) {
        const int cur = kb & 1;
        if (kb + 1 < NKB) {
            load_stage(sm0 + (cur ^ 1) * STAGE_B, kb + 1, tid, srcs);
            CP_COMMIT();
            CP_WAIT1();
        } else {
            CP_WAIT0();
        }
        __syncthreads();

        const uint32_t sb = sm0 + cur * STAGE_B;
        #pragma unroll
        for (int ks = 0; ks < 4; ks++) {
            uint32_t ra[2][2][4];
            #pragma unroll
            for (int s = 0; s < 2; s++)
                #pragma unroll
                for (int f = 0; f < 2; f++) {
                    int row = wm + f * 16 + (lane & 15);
                    int ch  = 2 * ks + (lane >> 4);
                    ldmx4(ra[s][f], sb + s * A_TILE_B + swz(row, ch));
                }
            uint32_t rb[2][2][4];
            #pragma unroll
            for (int s = 0; s < 2; s++)
                #pragma unroll
                for (int g = 0; g < 2; g++) {
                    int row = wn + g * 16 + (lane & 7) + ((lane >> 4) << 3);
                    int ch  = 2 * ks + ((lane >> 3) & 1);
                    ldmx4(rb[s][g], sb + 2 * A_TILE_B + s * B_TILE_B + swz(row, ch));
                }
            const int PA[3] = {0, 0, 1};
            const int PB[3] = {0, 1, 0};
            #pragma unroll
            for (int p = 0; p < 3; p++)
                #pragma unroll
                for (int f = 0; f < 2; f++)
                    #pragma unroll
                    for (int g = 0; g < 2; g++)
                        #pragma unroll
                        for (int h2 = 0; h2 < 2; h2++)
                            mma16816(acc[f][g * 2 + h2],
                                     ra[PA[p]][f], &rb[PB[p]][g][h2 * 2]);
        }
        __syncthreads();
    }

    // Epilogue: bias + store logits + per-row partial stats (max/argmax/sumexp)
    const int g8  = lane >> 2;
    const int tig = lane & 3;
    #pragma unroll
    for (int f = 0; f < 2; f++) {
        #pragma unroll
        for (int rr = 0; rr < 2; rr++) {
            const int mrow = m0 + wm + f * 16 + rr * 8 + g8;
            float* orow = g_logits + ((size_t)h * GM + mrow) * GN;
            float vv[8];
            float vmax = -1e30f;
            int   vidx = 0;
            #pragma unroll
            for (int nf = 0; nf < 4; nf++) {
                #pragma unroll
                for (int e = 0; e < 2; e++) {
                    const int ncol = n0 + wn + nf * 8 + tig * 2 + e;
                    float val = acc[f][nf][rr * 2 + e];
                    if (ncol < GN) {
                        val += bias[h * GN + ncol];
                        orow[ncol] = val;
                    } else {
                        val = -1e30f;
                    }
                    vv[nf * 2 + e] = val;
                    if (val > vmax) { vmax = val; vidx = ncol; }
                }
            }
            // quad reduce (tig lanes 0..3 within the quad): max with min-idx tiebreak
            #pragma unroll
            for (int msk = 1; msk <= 2; msk <<= 1) {
                float om = __shfl_xor_sync(0xffffffffu, vmax, msk);
                int   oi = __shfl_xor_sync(0xffffffffu, vidx, msk);
                if (om > vmax || (om == vmax && oi < vidx)) { vmax = om; vidx = oi; }
            }
            float s = 0.0f;
            #pragma unroll
            for (int i = 0; i < 8; i++) s += expf(vv[i] - vmax);
            s += __shfl_xor_sync(0xffffffffu, s, 1);
            s += __shfl_xor_sync(0xffffffffu, s, 2);
            if (tig == 0) {
                const int rl = f * 16 + rr * 8 + g8;   // 0..31 within wm group
                s_pm[wmg][rl][wnid] = vmax;
                s_ps[wmg][rl][wnid] = s;
                s_pi[wmg][rl][wnid] = vidx;
            }
        }
    }
    __syncthreads();

    if (tid < 64) {
        const int g2 = tid >> 5;    // wm group
        const int rl = tid & 31;
        float M = -1e30f; int I = 0;
        #pragma unroll
        for (int j = 0; j < 4; j++) {
            float m = s_pm[g2][rl][j];
            if (m > M) { M = m; I = s_pi[g2][rl][j]; }
        }
        float S = 0.0f;
        #pragma unroll
        for (int j = 0; j < 4; j++)
            S += s_ps[g2][rl][j] * expf(s_pm[g2][rl][j] - M);
        const int mrow = m0 + g2 * 32 + rl;
        const size_t pr = ((size_t)h * GM + mrow) * NTILES_N + blockIdx.x;
        g_pmax[pr] = M;
        g_psum[pr] = S;
        g_pidx[pr] = I;
    }
}

// ---------------------------------------------------------------------------
// Kernel C: combine per-tile partials -> lse, conf, argmax  (one thread/row)
// ---------------------------------------------------------------------------
__global__ __launch_bounds__(512) void sdn_combine_kernel()
{
    const int row = blockIdx.x * 512 + threadIdx.x;
    if (row >= GH * GM) return;
    const size_t base = (size_t)row * NTILES_N;
    float M = -1e30f; int I = 0;
    #pragma unroll
    for (int j = 0; j < NTILES_N; j++) {
        float m = g_pmax[base + j];
        if (m > M) { M = m; I = g_pidx[base + j]; }
    }
    float S = 0.0f;
    #pragma unroll
    for (int j = 0; j < NTILES_N; j++)
        S += g_psum[base + j] * expf(g_pmax[base + j] - M);
    const float lse = M + logf(S);
    g_lse[row]  = lse;
    g_conf[row] = 1.0f / S;          // = exp(M - lse)
    g_amax[row] = I;
}

// ---------------------------------------------------------------------------
// Kernel D: routing + loss + acc
// ---------------------------------------------------------------------------
__global__ __launch_bounds__(512) void sdn_route_kernel(
    const int* __restrict__ y_true, float* __restrict__ out)
{
    const int b = threadIdx.x;

    int   firstExit = -1;
    float bestc = -1e30f;
    int   besth = 0;
    #pragma unroll
    for (int h = 0; h < GH; h++) {
        float c = g_conf[h * GM + b];
        if (firstExit < 0 && c >= TAUC) firstExit = h;
        if (c > bestc) { bestc = c; besth = h; }
    }
    const int ex = (firstExit >= 0) ? firstExit : besth;
    g_exit[b] = ex;

    const int y = y_true[b];
    const size_t rowbase = ((size_t)ex * GM + b);
    const float logit_y = g_logits[rowbase * GN + y];
    const float loss_b  = -(logit_y - g_lse[rowbase]);
    const float acc_b   = (g_amax[rowbase] == y) ? 1.0f : 0.0f;

    out[GM * GN + b] = (float)ex;

    __shared__ float sl[512];
    __shared__ float sa[512];
    sl[b] = loss_b; sa[b] = acc_b;
    __syncthreads();
    for (int s = 256; s > 0; s >>= 1) {
        if (b < s) { sl[b] += sl[b + s]; sa[b] += sa[b + s]; }
        __syncthreads();
    }
    if (b == 0) {
        out[GM * GN + GM + 0] = sl[0] / (float)GM;
        out[GM * GN + GM + 1] = sa[0] / (float)GM;
    }
}

// ---------------------------------------------------------------------------
// Kernel E: gather routed outputs
// ---------------------------------------------------------------------------
__global__ __launch_bounds__(256) void sdn_gather_kernel(float* __restrict__ out)
{
    const int b  = blockIdx.x;
    const int ex = g_exit[b];
    const float4* src = reinterpret_cast<const float4*>(
        g_logits + ((size_t)ex * GM + b) * GN);
    float4* dst = reinterpret_cast<float4*>(out + (size_t)b * GN);
    for (int i = threadIdx.x; i < GN / 4; i += blockDim.x)
        dst[i] = src[i];
}

// ---------------------------------------------------------------------------
extern "C" void kernel_launch(void* const* d_in, const int* in_sizes, int n_in,
                              void* d_out, int out_size)
{
    const float* feats = (const float*)d_in[0];  // [6,512,2048]
    const float* W     = (const float*)d_in[1];  // [6,2048,1000]
    const float* bias  = (const float*)d_in[2];  // [6,1000]
    const int*   y     = (const int*)  d_in[3];  // [512]
    float* out = (float*)d_out;

    cudaFuncSetAttribute(sdn_mma_gemm, cudaFuncAttributeMaxDynamicSharedMemorySize, SMEM_DYN);

    convert_all_kernel<<<NFBLK + NWBLK, 256>>>(feats, W);
    sdn_mma_gemm<<<dim3(GNP / BN, GM / BM, GH), 256, SMEM_DYN>>>(bias);
    sdn_combine_kernel<<<(GH * GM + 511) / 512, 512>>>();
    sdn_route_kernel<<<1, 512>>>(y, out);
    sdn_gather_kernel<<<GM, 256>>>(out);
}

// round 12
// speedup vs baseline: 1.1356x; 1.0128x over previous
#include <cuda_runtime.h>
#include <cuda_bf16.h>
#include <cstdint>
#include <cstddef>

// ---------------------------------------------------------------------------
// Problem constants
// ---------------------------------------------------------------------------
#define GH 6
#define GM 512          // batch
#define GN 1000         // classes
#define GNP 1024        // padded classes
#define GK 2048         // feature dim
#define TAUC 0.5f
#define NTILES_N 8      // GNP / BN

// GEMM tiling (proven config: BK=64, 2-stage)
#define BM 64
#define BN 128
#define BK 64                     // bf16 elems per stage (128 B rows)
#define NKB (GK / BK)             // 32 stages
#define A_TILE_B (BM * 128)       // 8192 B per A split tile
#define B_TILE_B (BN * 128)       // 16384 B per B split tile
#define STAGE_B (2 * A_TILE_B + 2 * B_TILE_B)   // 49152 B
#define SMEM_DYN (2 * STAGE_B + 1024)

#define NFBLK 1536                // convert: feats blocks (4 float4 per thread)
#define NWBLK 3072                // convert: W blocks (16 c-tiles x 32 k-tiles x 6 h)

// ---------------------------------------------------------------------------
// Device-global scratch (no allocation allowed)
// ---------------------------------------------------------------------------
__device__ __align__(16) __nv_bfloat16 g_fa0[GH * GM * GK];
__device__ __align__(16) __nv_bfloat16 g_fa1[GH * GM * GK];
__device__ __align__(16) __nv_bfloat16 g_wt0[GH * GNP * GK];
__device__ __align__(16) __nv_bfloat16 g_wt1[GH * GNP * GK];
__device__ float g_logits[GH * GM * GN];
__device__ __align__(16) float g_pmax[GH * GM * NTILES_N];
__device__ __align__(16) float g_psum[GH * GM * NTILES_N];
__device__ __align__(16) int   g_pidx[GH * GM * NTILES_N];
__device__ int   g_exit  [GM];

// ---------------------------------------------------------------------------
// Helpers (baseline PTX only — safe on plain sm_103 target)
// ---------------------------------------------------------------------------
__device__ __forceinline__ uint32_t smem_to_u32(const void* p) {
    uint32_t a;
    asm("{ .reg .u64 t; cvta.to.shared.u64 t, %1; cvt.u32.u64 %0, t; }"
        : "=r"(a) : "l"(p));
    return a;
}

__device__ __forceinline__ void cp16(uint32_t s, const void* g) {
    asm volatile("cp.async.cg.shared.global [%0], [%1], 16;\n" :: "r"(s), "l"(g));
}
#define CP_COMMIT() asm volatile("cp.async.commit_group;\n" ::: "memory")
#define CP_WAIT1()  asm volatile("cp.async.wait_group 1;\n" ::: "memory")
#define CP_WAIT0()  asm volatile("cp.async.wait_group 0;\n" ::: "memory")

__device__ __forceinline__ void ldmx4(uint32_t* r, uint32_t addr) {
    asm volatile("ldmatrix.sync.aligned.m8n8.x4.shared.b16 {%0,%1,%2,%3}, [%4];"
                 : "=r"(r[0]), "=r"(r[1]), "=r"(r[2]), "=r"(r[3]) : "r"(addr));
}

__device__ __forceinline__ void mma16816(float* c, const uint32_t* a, const uint32_t* b) {
    asm volatile(
        "mma.sync.aligned.m16n8k16.row.col.f32.bf16.bf16.f32 "
        "{%0,%1,%2,%3}, {%4,%5,%6,%7}, {%8,%9}, {%0,%1,%2,%3};"
        : "+f"(c[0]), "+f"(c[1]), "+f"(c[2]), "+f"(c[3])
        : "r"(a[0]), "r"(a[1]), "r"(a[2]), "r"(a[3]), "r"(b[0]), "r"(b[1]));
}

// swizzled byte offset within a tile: 128B rows, 16B chunks, xor-8
__device__ __forceinline__ uint32_t swz(int row, int ch) {
    return (uint32_t)(row * 128 + ((ch ^ (row & 7)) << 4));
}

__device__ __forceinline__ void split2(float v, __nv_bfloat16& s0, __nv_bfloat16& s1) {
    s0 = __float2bfloat16_rn(v);
    s1 = __float2bfloat16_rn(v - __bfloat162float(s0));
}

// ---------------------------------------------------------------------------
// Kernel A: merged converts.
//   blocks [0, NFBLK)          : feats fp32 -> 2 bf16 splits (4 float4/thread)
//   blocks [NFBLK, NFBLK+NWBLK): W transpose+split, 64k x 64c tiles
// ---------------------------------------------------------------------------
__global__ __launch_bounds__(256) void convert_all_kernel(
    const float* __restrict__ feats, const float* __restrict__ W)
{
    const int bid = blockIdx.x;
    if (bid < NFBLK) {
        const int base = bid * 256 + threadIdx.x;
        #pragma unroll
        for (int i = 0; i < 4; i++) {
            const int gid = base + i * (NFBLK * 256);
            float4 v = reinterpret_cast<const float4*>(feats)[gid];
            __nv_bfloat16 a0[4], a1[4];
            split2(v.x, a0[0], a1[0]);
            split2(v.y, a0[1], a1[1]);
            split2(v.z, a0[2], a1[2]);
            split2(v.w, a0[3], a1[3]);
            reinterpret_cast<uint2*>(g_fa0)[gid] = *reinterpret_cast<uint2*>(a0);
            reinterpret_cast<uint2*>(g_fa1)[gid] = *reinterpret_cast<uint2*>(a1);
        }
    } else {
        const int wb = bid - NFBLK;                // 0..3071
        const int h  = wb >> 9;                    // 512 blocks per head
        const int k0 = ((wb >> 4) & 31) * 64;
        const int c0 = (wb & 15) * 64;
        __shared__ float t[64][65];
        const int tid  = threadIdx.x;
        const int lane = tid & 31;
        const int wid  = tid >> 5;                 // 0..7

        #pragma unroll
        for (int it = 0; it < 8; it++) {
            const int r = it * 8 + wid;            // local k
            #pragma unroll
            for (int half = 0; half < 2; half++) {
                const int c = c0 + half * 32 + lane;
                t[r][half * 32 + lane] =
                    (c < GN) ? W[((size_t)h * GK + (k0 + r)) * GN + c] : 0.0f;
            }
        }
        __syncthreads();

        #pragma unroll
        for (int p = 0; p < 8; p++) {
            const int cl = p * 8 + wid;            // local c 0..63
            const int cg = c0 + cl;
            float v0 = t[2 * lane][cl];
            float v1 = t[2 * lane + 1][cl];
            __nv_bfloat16 a0, a1, b0, b1;
            split2(v0, a0, a1);
            split2(v1, b0, b1);
            __nv_bfloat162 p0, p1;
            p0.x = a0; p0.y = b0;
            p1.x = a1; p1.y = b1;
            size_t widx = (((size_t)h * GNP + cg) * GK + k0 + 2 * lane) >> 1;
            reinterpret_cast<uint32_t*>(g_wt0)[widx] = *reinterpret_cast<uint32_t*>(&p0);
            reinterpret_cast<uint32_t*>(g_wt1)[widx] = *reinterpret_cast<uint32_t*>(&p1);
        }
    }
}

// ---------------------------------------------------------------------------
// Kernel B: mma.sync bf16 GEMM (3-product fp32 emulation) +
//           fused bias + per-tile softmax partial stats in the epilogue.
// ---------------------------------------------------------------------------
__device__ __forceinline__ void load_stage(
    uint32_t sb, int kb, int tid,
    const __nv_bfloat16* const* srcs)
{
    #pragma unroll
    for (int i = 0; i < 2; i++)
        #pragma unroll
        for (int it = 0; it < 2; it++) {
            const int q   = it * 256 + tid;
            const int row = q >> 3;
            const int ch  = q & 7;
            const __nv_bfloat16* g = srcs[i] + (size_t)row * GK + kb * BK + ch * 8;
            cp16(sb + i * A_TILE_B + swz(row, ch), g);
        }
    #pragma unroll
    for (int i = 0; i < 2; i++)
        #pragma unroll
        for (int it = 0; it < 4; it++) {
            const int q   = it * 256 + tid;
            const int row = q >> 3;
            const int ch  = q & 7;
            const __nv_bfloat16* g = srcs[2 + i] + (size_t)row * GK + kb * BK + ch * 8;
            cp16(sb + 2 * A_TILE_B + i * B_TILE_B + swz(row, ch), g);
        }
}

__global__ __launch_bounds__(256, 2) void sdn_mma_gemm(const float* __restrict__ bias)
{
    extern __shared__ char smem[];
    const uint32_t sm0 = (smem_to_u32(smem) + 1023u) & ~1023u;

    __shared__ float s_pm[2][32][4];
    __shared__ float s_ps[2][32][4];
    __shared__ int   s_pi[2][32][4];

    const int tid  = threadIdx.x;
    const int wid  = tid >> 5;
    const int lane = tid & 31;
    const int wm   = (wid & 1) * 32;        // 2 warps along m
    const int wn   = (wid >> 1) * 32;       // 4 warps along n
    const int wmg  = wid & 1;
    const int wnid = wid >> 1;

    const int h  = blockIdx.z;
    const int m0 = blockIdx.y * BM;
    const int n0 = blockIdx.x * BN;

    const __nv_bfloat16* srcs[4] = {
        g_fa0 + ((size_t)h * GM  + m0) * GK,
        g_fa1 + ((size_t)h * GM  + m0) * GK,
        g_wt0 + ((size_t)h * GNP + n0) * GK,
        g_wt1 + ((size_t)h * GNP + n0) * GK
    };

    float acc[2][4][4];
    #pragma unroll
    for (int f = 0; f < 2; f++)
        #pragma unroll
        for (int n = 0; n < 4; n++)
            #pragma unroll
            for (int e = 0; e < 4; e++) acc[f][n][e] = 0.0f;

    // Prologue
    load_stage(sm0, 0, tid, srcs);
    CP_COMMIT();

    #pragma unroll 1
    for (int kb = 0; kb < NKB; kb++) {
        const int cur = kb & 1;
        if (kb + 1 < NKB) {
            load_stage(sm0 + (cur ^ 1) * STAGE_B, kb + 1, tid, srcs);
            CP_COMMIT();
            CP_WAIT1();
        } else {
            CP_WAIT0();
        }
        __syncthreads();

        const uint32_t sb = sm0 + cur * STAGE_B;
        #pragma unroll
        for (int ks = 0; ks < 4; ks++) {
            uint32_t ra[2][2][4];
            #pragma unroll
            for (int s = 0; s < 2; s++)
                #pragma unroll
                for (int f = 0; f < 2; f++) {
                    int row = wm + f * 16 + (lane & 15);
                    int ch  = 2 * ks + (lane >> 4);
                    ldmx4(ra[s][f], sb + s * A_TILE_B + swz(row, ch));
                }
            uint32_t rb[2][2][4];
            #pragma unroll
            for (int s = 0; s < 2; s++)
                #pragma unroll
                for (int g = 0; g < 2; g++) {
                    int row = wn + g * 16 + (lane & 7) + ((lane >> 4) << 3);
                    int ch  = 2 * ks + ((lane >> 3) & 1);
                    ldmx4(rb[s][g], sb + 2 * A_TILE_B + s * B_TILE_B + swz(row, ch));
                }
            const int PA[3] = {0, 0, 1};
            const int PB[3] = {0, 1, 0};
            #pragma unroll
            for (int p = 0; p < 3; p++)
                #pragma unroll
                for (int f = 0; f < 2; f++)
                    #pragma unroll
                    for (int g = 0; g < 2; g++)
                        #pragma unroll
                        for (int h2 = 0; h2 < 2; h2++)
                            mma16816(acc[f][g * 2 + h2],
                                     ra[PA[p]][f], &rb[PB[p]][g][h2 * 2]);
        }
        __syncthreads();
    }

    // Epilogue: bias + store logits + per-row partial stats (max/argmax/sumexp)
    const int g8  = lane >> 2;
    const int tig = lane & 3;
    #pragma unroll
    for (int f = 0; f < 2; f++) {
        #pragma unroll
        for (int rr = 0; rr < 2; rr++) {
            const int mrow = m0 + wm + f * 16 + rr * 8 + g8;
            float* orow = g_logits + ((size_t)h * GM + mrow) * GN;
            float vv[8];
            float vmax = -1e30f;
            int   vidx = 0;
            #pragma unroll
            for (int nf = 0; nf < 4; nf++) {
                #pragma unroll
                for (int e = 0; e < 2; e++) {
                    const int ncol = n0 + wn + nf * 8 + tig * 2 + e;
                    float val = acc[f][nf][rr * 2 + e];
                    if (ncol < GN) {
                        val += bias[h * GN + ncol];
                        orow[ncol] = val;
                    } else {
                        val = -1e30f;
                    }
                    vv[nf * 2 + e] = val;
                    if (val > vmax) { vmax = val; vidx = ncol; }
                }
            }
            #pragma unroll
            for (int msk = 1; msk <= 2; msk <<= 1) {
                float om = __shfl_xor_sync(0xffffffffu, vmax, msk);
                int   oi = __shfl_xor_sync(0xffffffffu, vidx, msk);
                if (om > vmax || (om == vmax && oi < vidx)) { vmax = om; vidx = oi; }
            }
            float s = 0.0f;
            #pragma unroll
            for (int i = 0; i < 8; i++) s += expf(vv[i] - vmax);
            s += __shfl_xor_sync(0xffffffffu, s, 1);
            s += __shfl_xor_sync(0xffffffffu, s, 2);
            if (tig == 0) {
                const int rl = f * 16 + rr * 8 + g8;
                s_pm[wmg][rl][wnid] = vmax;
                s_ps[wmg][rl][wnid] = s;
                s_pi[wmg][rl][wnid] = vidx;
            }
        }
    }
    __syncthreads();

    if (tid < 64) {
        const int g2 = tid >> 5;
        const int rl = tid & 31;
        float M = -1e30f; int I = 0;
        #pragma unroll
        for (int j = 0; j < 4; j++) {
            float m = s_pm[g2][rl][j];
            if (m > M) { M = m; I = s_pi[g2][rl][j]; }
        }
        float S = 0.0f;
        #pragma unroll
        for (int j = 0; j < 4; j++)
            S += s_ps[g2][rl][j] * expf(s_pm[g2][rl][j] - M);
        const int mrow = m0 + g2 * 32 + rl;
        const size_t pr = ((size_t)h * GM + mrow) * NTILES_N + blockIdx.x;
        g_pmax[pr] = M;
        g_psum[pr] = S;
        g_pidx[pr] = I;
    }
}

// ---------------------------------------------------------------------------
// Kernel C: finalize — combine tile partials, route, loss, acc (one block)
// ---------------------------------------------------------------------------
__global__ __launch_bounds__(512) void sdn_finalize_kernel(
    const int* __restrict__ y_true, float* __restrict__ out)
{
    const int b = threadIdx.x;

    float lse[GH], conf[GH];
    int   amax[GH];
    #pragma unroll
    for (int h = 0; h < GH; h++) {
        const size_t base = ((size_t)h * GM + b) * NTILES_N;
        float4 m0 = *reinterpret_cast<const float4*>(&g_pmax[base]);
        float4 m1 = *reinterpret_cast<const float4*>(&g_pmax[base + 4]);
        int4   i0 = *reinterpret_cast<const int4*>(&g_pidx[base]);
        int4   i1 = *reinterpret_cast<const int4*>(&g_pidx[base + 4]);
        float4 s0 = *reinterpret_cast<const float4*>(&g_psum[base]);
        float4 s1 = *reinterpret_cast<const float4*>(&g_psum[base + 4]);
        const float mv[8] = {m0.x, m0.y, m0.z, m0.w, m1.x, m1.y, m1.z, m1.w};
        const int   iv[8] = {i0.x, i0.y, i0.z, i0.w, i1.x, i1.y, i1.z, i1.w};
        const float sv[8] = {s0.x, s0.y, s0.z, s0.w, s1.x, s1.y, s1.z, s1.w};
        float M = -1e30f; int I = 0;
        #pragma unroll
        for (int j = 0; j < 8; j++)
            if (mv[j] > M) { M = mv[j]; I = iv[j]; }
        float S = 0.0f;
        #pragma unroll
        for (int j = 0; j < 8; j++)
            S += sv[j] * expf(mv[j] - M);
        lse[h]  = M + logf(S);
        conf[h] = 1.0f / S;          // = exp(M - lse)
        amax[h] = I;
    }

    int   firstExit = -1;
    float bestc = -1e30f;
    int   besth = 0;
    #pragma unroll
    for (int h = 0; h < GH; h++) {
        const float c = conf[h];
        if (firstExit < 0 && c >= TAUC) firstExit = h;
        if (c > bestc) { bestc = c; besth = h; }
    }
    const int ex = (firstExit >= 0) ? firstExit : besth;
    g_exit[b] = ex;
    out[GM * GN + b] = (float)ex;

    const int y = y_true[b];
    const float logit_y = g_logits[((size_t)ex * GM + b) * GN + y];
    const float loss_b  = -(logit_y - lse[ex]);
    const float acc_b   = (amax[ex] == y) ? 1.0f : 0.0f;

    __shared__ float sl[512];
    __shared__ float sa[512];
    sl[b] = loss_b; sa[b] = acc_b;
    __syncthreads();
    for (int s = 256; s > 0; s >>= 1) {
        if (b < s) { sl[b] += sl[b + s]; sa[b] += sa[b + s]; }
        __syncthreads();
    }
    if (b == 0) {
        out[GM * GN + GM + 0] = sl[0] / (float)GM;
        out[GM * GN + GM + 1] = sa[0] / (float)GM;
    }
}

// ---------------------------------------------------------------------------
// Kernel D: gather routed outputs — flat coalesced copy
// ---------------------------------------------------------------------------
#define GATHER_BLOCKS 500   // 500*256 = 128000 = 512 rows * 250 float4
__global__ __launch_bounds__(256) void sdn_gather_kernel(float* __restrict__ out)
{
    const int idx = blockIdx.x * 256 + threadIdx.x;    // 0..127999
    const int b   = idx / 250;
    const int c   = idx - b * 250;
    const int ex  = g_exit[b];
    const float4* src = reinterpret_cast<const float4*>(
        g_logits + ((size_t)ex * GM + b) * GN);
    reinterpret_cast<float4*>(out + (size_t)b * GN)[c] = src[c];
}

// ---------------------------------------------------------------------------
extern "C" void kernel_launch(void* const* d_in, const int* in_sizes, int n_in,
                              void* d_out, int out_size)
{
    const float* feats = (const float*)d_in[0];  // [6,512,2048]
    const float* W     = (const float*)d_in[1];  // [6,2048,1000]
    const float* bias  = (const float*)d_in[2];  // [6,1000]
    const int*   y     = (const int*)  d_in[3];  // [512]
    float* out = (float*)d_out;

    cudaFuncSetAttribute(sdn_mma_gemm, cudaFuncAttributeMaxDynamicSharedMemorySize, SMEM_DYN);

    convert_all_kernel<<<NFBLK + NWBLK, 256>>>(feats, W);
    sdn_mma_gemm<<<dim3(GNP / BN, GM / BM, GH), 256, SMEM_DYN>>>(bias);
    sdn_finalize_kernel<<<1, 512>>>(y, out);
    sdn_gather_kernel<<<GATHER_BLOCKS, 256>>>(out);
}